// round 11
// baseline (speedup 1.0000x reference)
#include <cuda_runtime.h>
#include <cuda_bf16.h>
#include <cuda_fp16.h>
#include <cstdint>

// ======================= problem sizes (fixed by dataset) ====================
#define TOKENS 4096
#define IC     4096
#define OC     4096

// ======================= device scratch (no runtime alloc) ==================
__device__ uint16_t g_x16[(size_t)TOKENS * IC];  // 32 MB  x as fp16
__device__ uint16_t g_s16[(size_t)OC * IC];      // 32 MB  B = sign / (ow/s) fp16
__device__ float g_scale[OC];   // 0 -> 1 (exact: then all signs are 0)

// ======================= helpers =============================================
__device__ __forceinline__ uint32_t smem_u32(const void* p) {
    uint32_t a;
    asm("{ .reg .u64 t; cvta.to.shared.u64 t, %1; cvt.u32.u64 %0, t; }"
        : "=r"(a) : "l"(p));
    return a;
}

#define CP_ASYNC16(saddr, gaddr) \
    asm volatile("cp.async.cg.shared.global [%0], [%1], 16;" \
                 :: "r"(saddr), "l"(gaddr))
#define CP_COMMIT() asm volatile("cp.async.commit_group;" ::: "memory")
#define CP_WAIT2()  asm volatile("cp.async.wait_group 2;" ::: "memory")

#define LDMATRIX_X4(r0, r1, r2, r3, addr) \
    asm volatile("ldmatrix.sync.aligned.m8n8.x4.shared.b16 {%0,%1,%2,%3}, [%4];" \
                 : "=r"(r0), "=r"(r1), "=r"(r2), "=r"(r3) : "r"(addr))

#define MMA_F16(d, a, b0, b1) \
    asm volatile("mma.sync.aligned.m16n8k16.row.col.f32.f16.f16.f32 " \
                 "{%0,%1,%2,%3}, {%4,%5,%6,%7}, {%8,%9}, {%0,%1,%2,%3};" \
                 : "+f"((d)[0]), "+f"((d)[1]), "+f"((d)[2]), "+f"((d)[3]) \
                 : "r"((a)[0]), "r"((a)[1]), "r"((a)[2]), "r"((a)[3]), \
                   "r"(b0), "r"(b1))

// ======================= fused prep kernel ===================================
// blocks [0, OC)           : one w row each -> mean/abs-mean stats + fp16 B row
//                            (outlier cols replaced by ow/s_eff via smem map)
// blocks [OC, OC + 4096)   : 4096-elem chunk of x -> fp16
// Both phases are BW-bound; one grid lets them overlap across SMs.
__global__ void __launch_bounds__(256) prep_kernel(
    const float* __restrict__ w, const float* __restrict__ ow,
    const float* __restrict__ x, const int* __restrict__ idx, int nout) {
    __shared__ float red[256];
    __shared__ int16_t cmap[IC];   // column -> outlier slot (-1 if none)
    const int tid = threadIdx.x;
    const int b = blockIdx.x;

    if (b < OC) {
        // ---------- w path ----------
        // build per-block outlier map from idx
#pragma unroll
        for (int i = 0; i < IC / 256; ++i) cmap[tid + 256 * i] = -1;
        __syncthreads();
        for (int j = tid; j < nout; j += 256) cmap[idx[j]] = (int16_t)j;
        __syncthreads();

        const int o = b;
        const float4* row = (const float4*)(w + (size_t)o * IC);
        float4 v[4];
        float s = 0.f;
#pragma unroll
        for (int i = 0; i < 4; ++i) {
            v[i] = row[tid + 256 * i];
            s += v[i].x + v[i].y + v[i].z + v[i].w;
        }
        red[tid] = s;
        __syncthreads();
        for (int st = 128; st > 0; st >>= 1) {
            if (tid < st) red[tid] += red[tid + st];
            __syncthreads();
        }
        float mean = red[0] * (1.f / IC);
        __syncthreads();
        float a = 0.f;
#pragma unroll
        for (int i = 0; i < 4; ++i)
            a += fabsf(v[i].x - mean) + fabsf(v[i].y - mean) +
                 fabsf(v[i].z - mean) + fabsf(v[i].w - mean);
        red[tid] = a;
        __syncthreads();
        for (int st = 128; st > 0; st >>= 1) {
            if (tid < st) red[tid] += red[tid + st];
            __syncthreads();
        }
        float sc = red[0] * (1.f / IC);
        float s_eff = (sc == 0.f) ? 1.f : sc;   // sc==0 => all signs 0, 1 exact
        if (tid == 0) g_scale[o] = s_eff;
        float inv_s = 1.f / s_eff;
        const float* ow_row = ow + (size_t)o * nout;
#pragma unroll
        for (int i = 0; i < 4; ++i) {
            int e0 = (tid + 256 * i) * 4;
            float ev[4] = {v[i].x, v[i].y, v[i].z, v[i].w};
            uint16_t hv[4];
#pragma unroll
            for (int e = 0; e < 4; ++e) {
                int slot = cmap[e0 + e];
                float sv;
                if (slot < 0) {
                    float wc = ev[e] - mean;
                    sv = (wc > 0.f) ? 1.f : ((wc < 0.f) ? -1.f : 0.f);
                } else {
                    sv = ow_row[slot] * inv_s;
                }
                hv[e] = __half_as_ushort(__float2half_rn(sv));
            }
            uint2 pk;
            pk.x = (uint32_t)hv[0] | ((uint32_t)hv[1] << 16);
            pk.y = (uint32_t)hv[2] | ((uint32_t)hv[3] << 16);
            *(uint2*)(g_s16 + (size_t)o * IC + e0) = pk;
        }
    } else {
        // ---------- x path: convert 16 floats / thread ----------
        size_t base = ((size_t)(b - OC) * 256 + tid) * 16;
#pragma unroll
        for (int h = 0; h < 2; ++h) {
            size_t bb = base + h * 8;
            float4 v0 = *(const float4*)(x + bb);
            float4 v1 = *(const float4*)(x + bb + 4);
            float e[8] = {v0.x, v0.y, v0.z, v0.w, v1.x, v1.y, v1.z, v1.w};
            uint16_t hv[8];
#pragma unroll
            for (int k = 0; k < 8; ++k)
                hv[k] = __half_as_ushort(__float2half_rn(e[k]));
            uint4 pk;
            pk.x = (uint32_t)hv[0] | ((uint32_t)hv[1] << 16);
            pk.y = (uint32_t)hv[2] | ((uint32_t)hv[3] << 16);
            pk.z = (uint32_t)hv[4] | ((uint32_t)hv[5] << 16);
            pk.w = (uint32_t)hv[6] | ((uint32_t)hv[7] << 16);
            *(uint4*)(g_x16 + bb) = pk;
        }
    }
}

// ======================= GEMM (R10 config, frozen) ===========================
// CTA 128x128, BK=64, 3 stages, 2 CTAs/SM. 8 warps (2m x 4n), warp tile 64x32.
// K = 4096 (outliers folded into B). Epilogue: out = acc * s_o + bias.
static constexpr int NT = 64;
static constexpr int STAGE_BYTES = (128 + 128) * 64 * 2;  // 32768
static constexpr int OFF_B = 128 * 64 * 2;                 // 16384
static constexpr int SMEM_BYTES = 3 * STAGE_BYTES;         // 98304

__global__ void __launch_bounds__(256, 2)
gemm_kernel(float* __restrict__ out, const float* __restrict__ bias) {
    extern __shared__ __align__(1024) char smem[];
    const uint32_t sbase = smem_u32(smem);
    const int tid = threadIdx.x;
    const int bn = blockIdx.x, bm = blockIdx.y;
    const int wid = tid >> 5, lane = tid & 31;
    const int wm = wid >> 2, wn = wid & 3;

    float acc[4][4][4];
#pragma unroll
    for (int i = 0; i < 4; ++i)
#pragma unroll
        for (int j = 0; j < 4; ++j)
#pragma unroll
            for (int k = 0; k < 4; ++k) acc[i][j][k] = 0.f;

    const uint16_t* Abase = g_x16 + (size_t)bm * 128 * IC;
    const uint16_t* Bbase = g_s16 + (size_t)bn * 128 * IC;

    auto issue = [&](int kt, int s) {
        const uint16_t* a = Abase + kt * 64;
        const uint16_t* b = Bbase + kt * 64;
        uint32_t st = sbase + s * STAGE_BYTES;
#pragma unroll
        for (int i = 0; i < 4; ++i) {
            int c = tid + i * 256;
            int row = c >> 3, ch = c & 7;
            uint32_t so = (uint32_t)row * 128 + (uint32_t)((ch ^ (row & 7)) << 4);
            CP_ASYNC16(st + so, a + (size_t)row * IC + ch * 8);
            CP_ASYNC16(st + OFF_B + so, b + (size_t)row * IC + ch * 8);
        }
    };

    auto compute = [&](int s) {
        uint32_t stA = sbase + s * STAGE_BYTES;
        uint32_t stB = stA + OFF_B;
#pragma unroll
        for (int ks = 0; ks < 4; ++ks) {
            uint32_t bfr[2][4];
#pragma unroll
            for (int nj = 0; nj < 2; ++nj) {
                int row = wn * 32 + nj * 16 + (lane & 7) + (((lane >> 4) & 1) << 3);
                int ch = ks * 2 + ((lane >> 3) & 1);
                uint32_t ad = stB + (uint32_t)row * 128 +
                              (uint32_t)((ch ^ (row & 7)) << 4);
                LDMATRIX_X4(bfr[nj][0], bfr[nj][1], bfr[nj][2], bfr[nj][3], ad);
            }
            uint32_t afr[4][4];
#pragma unroll
            for (int mi = 0; mi < 4; ++mi) {
                int row = wm * 64 + mi * 16 + (lane & 15);
                int ch = ks * 2 + (lane >> 4);
                uint32_t ad = stA + (uint32_t)row * 128 +
                              (uint32_t)((ch ^ (row & 7)) << 4);
                LDMATRIX_X4(afr[mi][0], afr[mi][1], afr[mi][2], afr[mi][3], ad);
            }
#pragma unroll
            for (int mi = 0; mi < 4; ++mi)
#pragma unroll
                for (int nf = 0; nf < 4; ++nf)
                    MMA_F16(acc[mi][nf], afr[mi],
                            bfr[nf >> 1][(nf & 1) * 2],
                            bfr[nf >> 1][(nf & 1) * 2 + 1]);
        }
    };

    issue(0, 0); CP_COMMIT();
    issue(1, 1); CP_COMMIT();
    for (int kt = 0; kt < NT; ++kt) {
        if (kt + 2 < NT) issue(kt + 2, (kt + 2) % 3);
        CP_COMMIT();
        CP_WAIT2();
        __syncthreads();
        compute(kt % 3);
        __syncthreads();
    }

    // ---- epilogue: out = acc * s_o + bias ------------------------------
#pragma unroll
    for (int nf = 0; nf < 4; ++nf) {
        int col = bn * 128 + wn * 32 + (nf >> 1) * 16 + (nf & 1) * 8 + 2 * (lane & 3);
        float s0 = g_scale[col], s1 = g_scale[col + 1];
        float b0 = __ldg(bias + col), b1 = __ldg(bias + col + 1);
#pragma unroll
        for (int mi = 0; mi < 4; ++mi) {
            int r0 = bm * 128 + wm * 64 + mi * 16 + (lane >> 2);
            float2 v0 = make_float2(acc[mi][nf][0] * s0 + b0,
                                    acc[mi][nf][1] * s1 + b1);
            *(float2*)(out + (size_t)r0 * OC + col) = v0;
            float2 v1 = make_float2(acc[mi][nf][2] * s0 + b0,
                                    acc[mi][nf][3] * s1 + b1);
            *(float2*)(out + (size_t)(r0 + 8) * OC + col) = v1;
        }
    }
}

// ======================= launcher ============================================
extern "C" void kernel_launch(void* const* d_in, const int* in_sizes, int n_in,
                              void* d_out, int out_size) {
    const float* x = (const float*)d_in[0];
    const float* w = (const float*)d_in[1];
    const float* bias = (const float*)d_in[2];
    const float* ow = (const float*)d_in[3];
    const int* idx = (const int*)d_in[4];
    float* out = (float*)d_out;
    int nout = in_sizes[4];

    static bool attr_set = false;
    if (!attr_set) {
        cudaFuncSetAttribute(gemm_kernel,
                             cudaFuncAttributeMaxDynamicSharedMemorySize, SMEM_BYTES);
        attr_set = true;
    }

    // One fused prep launch: OC w-row blocks + TOKENS*IC/4096 x-chunk blocks.
    prep_kernel<<<OC + (int)((size_t)TOKENS * IC / 4096), 256>>>(w, ow, x, idx, nout);

    dim3 grid(OC / 128, TOKENS / 128);
    gemm_kernel<<<grid, 256, SMEM_BYTES>>>(out, bias);
}

// round 12
// speedup vs baseline: 1.5165x; 1.5165x over previous
#include <cuda_runtime.h>
#include <cuda_bf16.h>
#include <cuda_fp16.h>
#include <cstdint>

// ======================= problem sizes (fixed by dataset) ====================
#define TOKENS 4096
#define IC     4096
#define OC     4096

// ======================= device scratch (no runtime alloc) ==================
__device__ uint16_t g_x16[(size_t)TOKENS * IC];  // 32 MB  x as fp16
__device__ uint16_t g_s16[(size_t)OC * IC];      // 32 MB  B = sign / (ow/s) fp16
__device__ float g_scale[OC];   // 0 -> 1 (exact: then all signs are 0)

// ======================= helpers =============================================
__device__ __forceinline__ uint32_t smem_u32(const void* p) {
    uint32_t a;
    asm("{ .reg .u64 t; cvta.to.shared.u64 t, %1; cvt.u32.u64 %0, t; }"
        : "=r"(a) : "l"(p));
    return a;
}

#define CP_ASYNC16(saddr, gaddr) \
    asm volatile("cp.async.cg.shared.global [%0], [%1], 16;" \
                 :: "r"(saddr), "l"(gaddr))
#define CP_COMMIT() asm volatile("cp.async.commit_group;" ::: "memory")
#define CP_WAIT1()  asm volatile("cp.async.wait_group 1;" ::: "memory")

#define LDMATRIX_X4(r0, r1, r2, r3, addr) \
    asm volatile("ldmatrix.sync.aligned.m8n8.x4.shared.b16 {%0,%1,%2,%3}, [%4];" \
                 : "=r"(r0), "=r"(r1), "=r"(r2), "=r"(r3) : "r"(addr))

#define MMA_F16(d, a, b0, b1) \
    asm volatile("mma.sync.aligned.m16n8k16.row.col.f32.f16.f16.f32 " \
                 "{%0,%1,%2,%3}, {%4,%5,%6,%7}, {%8,%9}, {%0,%1,%2,%3};" \
                 : "+f"((d)[0]), "+f"((d)[1]), "+f"((d)[2]), "+f"((d)[3]) \
                 : "r"((a)[0]), "r"((a)[1]), "r"((a)[2]), "r"((a)[3]), \
                   "r"(b0), "r"(b1))

// ======================= prep kernels ========================================
// Per-row mean & abs-mean of w + fp16 B row (outlier cols = ow/s_eff).
// Outlier map built per-block in smem from idx (no global map kernels).
__global__ void __launch_bounds__(256) stats_ws_kernel(
    const float* __restrict__ w, const float* __restrict__ ow,
    const int* __restrict__ idx, int nout) {
    __shared__ float red[256];
    __shared__ int16_t cmap[IC];   // column -> outlier slot (-1 if none)
    const int o = blockIdx.x, tid = threadIdx.x;

#pragma unroll
    for (int i = 0; i < IC / 256; ++i) cmap[tid + 256 * i] = -1;
    __syncthreads();
    for (int j = tid; j < nout; j += 256) cmap[idx[j]] = (int16_t)j;
    __syncthreads();

    const float4* row = (const float4*)(w + (size_t)o * IC);
    float4 v[4];
    float s = 0.f;
#pragma unroll
    for (int i = 0; i < 4; ++i) {
        v[i] = row[tid + 256 * i];
        s += v[i].x + v[i].y + v[i].z + v[i].w;
    }
    red[tid] = s;
    __syncthreads();
    for (int st = 128; st > 0; st >>= 1) {
        if (tid < st) red[tid] += red[tid + st];
        __syncthreads();
    }
    float mean = red[0] * (1.f / IC);
    __syncthreads();
    float a = 0.f;
#pragma unroll
    for (int i = 0; i < 4; ++i)
        a += fabsf(v[i].x - mean) + fabsf(v[i].y - mean) +
             fabsf(v[i].z - mean) + fabsf(v[i].w - mean);
    red[tid] = a;
    __syncthreads();
    for (int st = 128; st > 0; st >>= 1) {
        if (tid < st) red[tid] += red[tid + st];
        __syncthreads();
    }
    float sc = red[0] * (1.f / IC);
    float s_eff = (sc == 0.f) ? 1.f : sc;   // sc==0 => all signs 0, so 1 exact
    if (tid == 0) g_scale[o] = s_eff;
    float inv_s = 1.f / s_eff;
    const float* ow_row = ow + (size_t)o * nout;
#pragma unroll
    for (int i = 0; i < 4; ++i) {
        int e0 = (tid + 256 * i) * 4;
        float ev[4] = {v[i].x, v[i].y, v[i].z, v[i].w};
        uint16_t hv[4];
#pragma unroll
        for (int e = 0; e < 4; ++e) {
            int slot = cmap[e0 + e];
            float sv;
            if (slot < 0) {
                float wc = ev[e] - mean;
                sv = (wc > 0.f) ? 1.f : ((wc < 0.f) ? -1.f : 0.f);
            } else {
                sv = ow_row[slot] * inv_s;
            }
            hv[e] = __half_as_ushort(__float2half_rn(sv));
        }
        uint2 pk;
        pk.x = (uint32_t)hv[0] | ((uint32_t)hv[1] << 16);
        pk.y = (uint32_t)hv[2] | ((uint32_t)hv[3] << 16);
        *(uint2*)(g_s16 + (size_t)o * IC + e0) = pk;
    }
}

__global__ void build_x_kernel(const float* __restrict__ x) {
    size_t base = ((size_t)blockIdx.x * 256 + threadIdx.x) * 8;
    float4 v0 = *(const float4*)(x + base);
    float4 v1 = *(const float4*)(x + base + 4);
    float e[8] = {v0.x, v0.y, v0.z, v0.w, v1.x, v1.y, v1.z, v1.w};
    uint16_t hv[8];
#pragma unroll
    for (int k = 0; k < 8; ++k) hv[k] = __half_as_ushort(__float2half_rn(e[k]));
    uint4 pk;
    pk.x = (uint32_t)hv[0] | ((uint32_t)hv[1] << 16);
    pk.y = (uint32_t)hv[2] | ((uint32_t)hv[3] << 16);
    pk.z = (uint32_t)hv[4] | ((uint32_t)hv[5] << 16);
    pk.w = (uint32_t)hv[6] | ((uint32_t)hv[7] << 16);
    *(uint4*)(g_x16 + base) = pk;
}

// ======================= GEMM ================================================
// CTA 128x128, BK=64, 3 stages, 2 CTAs/SM. 8 warps (2m x 4n), warp tile 64x32.
// Single-barrier loop: wait_group 1 -> sync -> issue(kt+2) -> compute(kt).
// issue(kt+2) writes stage (kt-1)%3, fully consumed before this iter's sync.
static constexpr int NT = 64;
static constexpr int STAGE_BYTES = (128 + 128) * 64 * 2;  // 32768
static constexpr int OFF_B = 128 * 64 * 2;                 // 16384
static constexpr int SMEM_BYTES = 3 * STAGE_BYTES;         // 98304

__global__ void __launch_bounds__(256, 2)
gemm_kernel(float* __restrict__ out, const float* __restrict__ bias) {
    extern __shared__ __align__(1024) char smem[];
    const uint32_t sbase = smem_u32(smem);
    const int tid = threadIdx.x;
    const int bn = blockIdx.x, bm = blockIdx.y;
    const int wid = tid >> 5, lane = tid & 31;
    const int wm = wid >> 2, wn = wid & 3;

    float acc[4][4][4];
#pragma unroll
    for (int i = 0; i < 4; ++i)
#pragma unroll
        for (int j = 0; j < 4; ++j)
#pragma unroll
            for (int k = 0; k < 4; ++k) acc[i][j][k] = 0.f;

    const uint16_t* Abase = g_x16 + (size_t)bm * 128 * IC;
    const uint16_t* Bbase = g_s16 + (size_t)bn * 128 * IC;

    auto issue = [&](int kt, int s) {
        const uint16_t* a = Abase + kt * 64;
        const uint16_t* b = Bbase + kt * 64;
        uint32_t st = sbase + s * STAGE_BYTES;
#pragma unroll
        for (int i = 0; i < 4; ++i) {
            int c = tid + i * 256;
            int row = c >> 3, ch = c & 7;
            uint32_t so = (uint32_t)row * 128 + (uint32_t)((ch ^ (row & 7)) << 4);
            CP_ASYNC16(st + so, a + (size_t)row * IC + ch * 8);
            CP_ASYNC16(st + OFF_B + so, b + (size_t)row * IC + ch * 8);
        }
    };

    auto compute = [&](int s) {
        uint32_t stA = sbase + s * STAGE_BYTES;
        uint32_t stB = stA + OFF_B;
#pragma unroll
        for (int ks = 0; ks < 4; ++ks) {
            uint32_t bfr[2][4];
#pragma unroll
            for (int nj = 0; nj < 2; ++nj) {
                int row = wn * 32 + nj * 16 + (lane & 7) + (((lane >> 4) & 1) << 3);
                int ch = ks * 2 + ((lane >> 3) & 1);
                uint32_t ad = stB + (uint32_t)row * 128 +
                              (uint32_t)((ch ^ (row & 7)) << 4);
                LDMATRIX_X4(bfr[nj][0], bfr[nj][1], bfr[nj][2], bfr[nj][3], ad);
            }
            uint32_t afr[4][4];
#pragma unroll
            for (int mi = 0; mi < 4; ++mi) {
                int row = wm * 64 + mi * 16 + (lane & 15);
                int ch = ks * 2 + (lane >> 4);
                uint32_t ad = stA + (uint32_t)row * 128 +
                              (uint32_t)((ch ^ (row & 7)) << 4);
                LDMATRIX_X4(afr[mi][0], afr[mi][1], afr[mi][2], afr[mi][3], ad);
            }
#pragma unroll
            for (int mi = 0; mi < 4; ++mi)
#pragma unroll
                for (int nf = 0; nf < 4; ++nf)
                    MMA_F16(acc[mi][nf], afr[mi],
                            bfr[nf >> 1][(nf & 1) * 2],
                            bfr[nf >> 1][(nf & 1) * 2 + 1]);
        }
    };

    issue(0, 0); CP_COMMIT();
    issue(1, 1); CP_COMMIT();
    for (int kt = 0; kt < NT; ++kt) {
        CP_WAIT1();            // oldest outstanding group (kt) complete
        __syncthreads();       // all warps done with compute(kt-1)
        if (kt + 2 < NT) {
            issue(kt + 2, (kt + 2) % 3);   // writes stage (kt-1)%3: free
            CP_COMMIT();
        }
        compute(kt % 3);
    }

    // ---- epilogue: out = acc * s_o + bias ------------------------------
#pragma unroll
    for (int nf = 0; nf < 4; ++nf) {
        int col = bn * 128 + wn * 32 + (nf >> 1) * 16 + (nf & 1) * 8 + 2 * (lane & 3);
        float s0 = g_scale[col], s1 = g_scale[col + 1];
        float b0 = __ldg(bias + col), b1 = __ldg(bias + col + 1);
#pragma unroll
        for (int mi = 0; mi < 4; ++mi) {
            int r0 = bm * 128 + wm * 64 + mi * 16 + (lane >> 2);
            float2 v0 = make_float2(acc[mi][nf][0] * s0 + b0,
                                    acc[mi][nf][1] * s1 + b1);
            *(float2*)(out + (size_t)r0 * OC + col) = v0;
            float2 v1 = make_float2(acc[mi][nf][2] * s0 + b0,
                                    acc[mi][nf][3] * s1 + b1);
            *(float2*)(out + (size_t)(r0 + 8) * OC + col) = v1;
        }
    }
}

// ======================= launcher ============================================
extern "C" void kernel_launch(void* const* d_in, const int* in_sizes, int n_in,
                              void* d_out, int out_size) {
    const float* x = (const float*)d_in[0];
    const float* w = (const float*)d_in[1];
    const float* bias = (const float*)d_in[2];
    const float* ow = (const float*)d_in[3];
    const int* idx = (const int*)d_in[4];
    float* out = (float*)d_out;
    int nout = in_sizes[4];

    static bool attr_set = false;
    if (!attr_set) {
        cudaFuncSetAttribute(gemm_kernel,
                             cudaFuncAttributeMaxDynamicSharedMemorySize, SMEM_BYTES);
        attr_set = true;
    }

    stats_ws_kernel<<<OC, 256>>>(w, ow, idx, nout);
    build_x_kernel<<<(unsigned)((size_t)TOKENS * IC / 2048), 256>>>(x);

    dim3 grid(OC / 128, TOKENS / 128);
    gemm_kernel<<<grid, 256, SMEM_BYTES>>>(out, bias);
}

// round 13
// speedup vs baseline: 1.5391x; 1.0149x over previous
#include <cuda_runtime.h>
#include <cuda_bf16.h>
#include <cuda_fp16.h>
#include <cstdint>

// ======================= problem sizes (fixed by dataset) ====================
#define TOKENS 4096
#define IC     4096
#define OC     4096

// ======================= device scratch (no runtime alloc) ==================
__device__ uint16_t g_x16[(size_t)TOKENS * IC];  // 32 MB  x as fp16
__device__ uint16_t g_s16[(size_t)OC * IC];      // 32 MB  B = sign / (ow/s) fp16
__device__ float g_scale[OC];   // 0 -> 1 (exact: then all signs are 0)

// ======================= helpers =============================================
__device__ __forceinline__ uint32_t smem_u32(const void* p) {
    uint32_t a;
    asm("{ .reg .u64 t; cvta.to.shared.u64 t, %1; cvt.u32.u64 %0, t; }"
        : "=r"(a) : "l"(p));
    return a;
}

#define CP_ASYNC16(saddr, gaddr) \
    asm volatile("cp.async.cg.shared.global [%0], [%1], 16;" \
                 :: "r"(saddr), "l"(gaddr))
#define CP_COMMIT() asm volatile("cp.async.commit_group;" ::: "memory")
#define CP_WAIT1()  asm volatile("cp.async.wait_group 1;" ::: "memory")

#define LDMATRIX_X4(r0, r1, r2, r3, addr) \
    asm volatile("ldmatrix.sync.aligned.m8n8.x4.shared.b16 {%0,%1,%2,%3}, [%4];" \
                 : "=r"(r0), "=r"(r1), "=r"(r2), "=r"(r3) : "r"(addr))

#define MMA_F16(d, a, b0, b1) \
    asm volatile("mma.sync.aligned.m16n8k16.row.col.f32.f16.f16.f32 " \
                 "{%0,%1,%2,%3}, {%4,%5,%6,%7}, {%8,%9}, {%0,%1,%2,%3};" \
                 : "+f"((d)[0]), "+f"((d)[1]), "+f"((d)[2]), "+f"((d)[3]) \
                 : "r"((a)[0]), "r"((a)[1]), "r"((a)[2]), "r"((a)[3]), \
                   "r"(b0), "r"(b1))

// ======================= prep kernels ========================================
// Per-row mean & abs-mean of w + fp16 B row. Two-phase: (1) vectorized pure
// sign writes for all columns (no lookups/branches), barrier, (2) threads
// 0..nout-1 overwrite the outlier columns with fp16(ow/s_eff).
__global__ void __launch_bounds__(256) stats_ws_kernel(
    const float* __restrict__ w, const float* __restrict__ ow,
    const int* __restrict__ idx, int nout) {
    __shared__ float red[16];
    const int o = blockIdx.x, tid = threadIdx.x;
    const int lane = tid & 31, warp = tid >> 5;

    const float4* row = (const float4*)(w + (size_t)o * IC);
    float4 v[4];
    float s = 0.f;
#pragma unroll
    for (int i = 0; i < 4; ++i) {
        v[i] = row[tid + 256 * i];
        s += v[i].x + v[i].y + v[i].z + v[i].w;
    }
    // warp-shuffle sum reduction
#pragma unroll
    for (int d = 16; d > 0; d >>= 1) s += __shfl_xor_sync(0xffffffffu, s, d);
    if (lane == 0) red[warp] = s;
    __syncthreads();
    if (warp == 0) {
        float t = (lane < 8) ? red[lane] : 0.f;
#pragma unroll
        for (int d = 4; d > 0; d >>= 1) t += __shfl_xor_sync(0xffffffffu, t, d);
        if (lane == 0) red[8] = t;
    }
    __syncthreads();
    float mean = red[8] * (1.f / IC);

    float a = 0.f;
#pragma unroll
    for (int i = 0; i < 4; ++i)
        a += fabsf(v[i].x - mean) + fabsf(v[i].y - mean) +
             fabsf(v[i].z - mean) + fabsf(v[i].w - mean);
#pragma unroll
    for (int d = 16; d > 0; d >>= 1) a += __shfl_xor_sync(0xffffffffu, a, d);
    if (lane == 0) red[warp] = a;
    __syncthreads();
    if (warp == 0) {
        float t = (lane < 8) ? red[lane] : 0.f;
#pragma unroll
        for (int d = 4; d > 0; d >>= 1) t += __shfl_xor_sync(0xffffffffu, t, d);
        if (lane == 0) red[9] = t;
    }
    __syncthreads();
    float sc = red[9] * (1.f / IC);
    float s_eff = (sc == 0.f) ? 1.f : sc;   // sc==0 => all signs 0, so 1 exact
    if (tid == 0) g_scale[o] = s_eff;

    // Phase 1: pure sign row, vectorized, branch-free
#pragma unroll
    for (int i = 0; i < 4; ++i) {
        int e0 = (tid + 256 * i) * 4;
        float ev[4] = {v[i].x, v[i].y, v[i].z, v[i].w};
        uint16_t hv[4];
#pragma unroll
        for (int e = 0; e < 4; ++e) {
            float wc = ev[e] - mean;
            float sv = (wc > 0.f) ? 1.f : ((wc < 0.f) ? -1.f : 0.f);
            hv[e] = __half_as_ushort(__float2half_rn(sv));
        }
        uint2 pk;
        pk.x = (uint32_t)hv[0] | ((uint32_t)hv[1] << 16);
        pk.y = (uint32_t)hv[2] | ((uint32_t)hv[3] << 16);
        *(uint2*)(g_s16 + (size_t)o * IC + e0) = pk;
    }

    // Phase 2: overwrite outlier columns (ordering via block barrier)
    __syncthreads();
    if (tid < nout) {
        float sv = ow[(size_t)o * nout + tid] / s_eff;
        g_s16[(size_t)o * IC + idx[tid]] =
            __half_as_ushort(__float2half_rn(sv));
    }
}

__global__ void build_x_kernel(const float* __restrict__ x) {
    size_t base = ((size_t)blockIdx.x * 256 + threadIdx.x) * 8;
    float4 v0 = *(const float4*)(x + base);
    float4 v1 = *(const float4*)(x + base + 4);
    float e[8] = {v0.x, v0.y, v0.z, v0.w, v1.x, v1.y, v1.z, v1.w};
    uint16_t hv[8];
#pragma unroll
    for (int k = 0; k < 8; ++k) hv[k] = __half_as_ushort(__float2half_rn(e[k]));
    uint4 pk;
    pk.x = (uint32_t)hv[0] | ((uint32_t)hv[1] << 16);
    pk.y = (uint32_t)hv[2] | ((uint32_t)hv[3] << 16);
    pk.z = (uint32_t)hv[4] | ((uint32_t)hv[5] << 16);
    pk.w = (uint32_t)hv[6] | ((uint32_t)hv[7] << 16);
    *(uint4*)(g_x16 + base) = pk;
}

// ======================= GEMM (R12 config, frozen) ===========================
// CTA 128x128, BK=64, 3 stages, 2 CTAs/SM. 8 warps (2m x 4n), warp tile 64x32.
// Single-barrier loop: wait_group 1 -> sync -> issue(kt+2) -> compute(kt).
static constexpr int NT = 64;
static constexpr int STAGE_BYTES = (128 + 128) * 64 * 2;  // 32768
static constexpr int OFF_B = 128 * 64 * 2;                 // 16384
static constexpr int SMEM_BYTES = 3 * STAGE_BYTES;         // 98304

__global__ void __launch_bounds__(256, 2)
gemm_kernel(float* __restrict__ out, const float* __restrict__ bias) {
    extern __shared__ __align__(1024) char smem[];
    const uint32_t sbase = smem_u32(smem);
    const int tid = threadIdx.x;
    const int bn = blockIdx.x, bm = blockIdx.y;
    const int wid = tid >> 5, lane = tid & 31;
    const int wm = wid >> 2, wn = wid & 3;

    float acc[4][4][4];
#pragma unroll
    for (int i = 0; i < 4; ++i)
#pragma unroll
        for (int j = 0; j < 4; ++j)
#pragma unroll
            for (int k = 0; k < 4; ++k) acc[i][j][k] = 0.f;

    const uint16_t* Abase = g_x16 + (size_t)bm * 128 * IC;
    const uint16_t* Bbase = g_s16 + (size_t)bn * 128 * IC;

    auto issue = [&](int kt, int s) {
        const uint16_t* a = Abase + kt * 64;
        const uint16_t* b = Bbase + kt * 64;
        uint32_t st = sbase + s * STAGE_BYTES;
#pragma unroll
        for (int i = 0; i < 4; ++i) {
            int c = tid + i * 256;
            int row = c >> 3, ch = c & 7;
            uint32_t so = (uint32_t)row * 128 + (uint32_t)((ch ^ (row & 7)) << 4);
            CP_ASYNC16(st + so, a + (size_t)row * IC + ch * 8);
            CP_ASYNC16(st + OFF_B + so, b + (size_t)row * IC + ch * 8);
        }
    };

    auto compute = [&](int s) {
        uint32_t stA = sbase + s * STAGE_BYTES;
        uint32_t stB = stA + OFF_B;
#pragma unroll
        for (int ks = 0; ks < 4; ++ks) {
            uint32_t bfr[2][4];
#pragma unroll
            for (int nj = 0; nj < 2; ++nj) {
                int row = wn * 32 + nj * 16 + (lane & 7) + (((lane >> 4) & 1) << 3);
                int ch = ks * 2 + ((lane >> 3) & 1);
                uint32_t ad = stB + (uint32_t)row * 128 +
                              (uint32_t)((ch ^ (row & 7)) << 4);
                LDMATRIX_X4(bfr[nj][0], bfr[nj][1], bfr[nj][2], bfr[nj][3], ad);
            }
            uint32_t afr[4][4];
#pragma unroll
            for (int mi = 0; mi < 4; ++mi) {
                int row = wm * 64 + mi * 16 + (lane & 15);
                int ch = ks * 2 + (lane >> 4);
                uint32_t ad = stA + (uint32_t)row * 128 +
                              (uint32_t)((ch ^ (row & 7)) << 4);
                LDMATRIX_X4(afr[mi][0], afr[mi][1], afr[mi][2], afr[mi][3], ad);
            }
#pragma unroll
            for (int mi = 0; mi < 4; ++mi)
#pragma unroll
                for (int nf = 0; nf < 4; ++nf)
                    MMA_F16(acc[mi][nf], afr[mi],
                            bfr[nf >> 1][(nf & 1) * 2],
                            bfr[nf >> 1][(nf & 1) * 2 + 1]);
        }
    };

    issue(0, 0); CP_COMMIT();
    issue(1, 1); CP_COMMIT();
    for (int kt = 0; kt < NT; ++kt) {
        CP_WAIT1();            // oldest outstanding group (kt) complete
        __syncthreads();       // all warps done with compute(kt-1)
        if (kt + 2 < NT) {
            issue(kt + 2, (kt + 2) % 3);   // writes stage (kt-1)%3: free
            CP_COMMIT();
        }
        compute(kt % 3);
    }

    // ---- epilogue: out = acc * s_o + bias ------------------------------
#pragma unroll
    for (int nf = 0; nf < 4; ++nf) {
        int col = bn * 128 + wn * 32 + (nf >> 1) * 16 + (nf & 1) * 8 + 2 * (lane & 3);
        float s0 = g_scale[col], s1 = g_scale[col + 1];
        float b0 = __ldg(bias + col), b1 = __ldg(bias + col + 1);
#pragma unroll
        for (int mi = 0; mi < 4; ++mi) {
            int r0 = bm * 128 + wm * 64 + mi * 16 + (lane >> 2);
            float2 v0 = make_float2(acc[mi][nf][0] * s0 + b0,
                                    acc[mi][nf][1] * s1 + b1);
            *(float2*)(out + (size_t)r0 * OC + col) = v0;
            float2 v1 = make_float2(acc[mi][nf][2] * s0 + b0,
                                    acc[mi][nf][3] * s1 + b1);
            *(float2*)(out + (size_t)(r0 + 8) * OC + col) = v1;
        }
    }
}

// ======================= launcher ============================================
extern "C" void kernel_launch(void* const* d_in, const int* in_sizes, int n_in,
                              void* d_out, int out_size) {
    const float* x = (const float*)d_in[0];
    const float* w = (const float*)d_in[1];
    const float* bias = (const float*)d_in[2];
    const float* ow = (const float*)d_in[3];
    const int* idx = (const int*)d_in[4];
    float* out = (float*)d_out;
    int nout = in_sizes[4];

    static bool attr_set = false;
    if (!attr_set) {
        cudaFuncSetAttribute(gemm_kernel,
                             cudaFuncAttributeMaxDynamicSharedMemorySize, SMEM_BYTES);
        attr_set = true;
    }

    stats_ws_kernel<<<OC, 256>>>(w, ow, idx, nout);
    build_x_kernel<<<(unsigned)((size_t)TOKENS * IC / 2048), 256>>>(x);

    dim3 grid(OC / 128, TOKENS / 128);
    gemm_kernel<<<grid, 256, SMEM_BYTES>>>(out, bias);
}